// round 12
// baseline (speedup 1.0000x reference)
#include <cuda_runtime.h>

// Noisy LIF spiking neuron scan — FINAL (= R7, the measured optimum).
//   u = 0.5*u + x[t] - 0.5*noise[t] ; o = (u > 1) ; u = o ? 0 : u
//
// Exhaustively mapped surface (R1-R9), 768 MB irreducible HBM traffic:
//   - 256-bit v8 ld/st, plain cache policy: DRAM=84.8%, ncu 114.2us (BEST)
//   - float4 variants: <= 84.1% ; every hint (.cs/.wt), every ILP
//     restructure (CH-batch, prefetch), every grid reshape: strictly worse.
// Residual 15% of DRAM cycles = refresh + R/W turnaround on a 2:1 stream,
// not addressable from the kernel. One thread owns 8 adjacent lanes;
// 131072 threads, 512 CTAs x 256, regs=40, single wave.

static constexpr int B  = 16;
static constexpr int T  = 64;
static constexpr int N  = 65536;
static constexpr int N8 = N / 8;     // float8 lanes per (b, t) row = 8192

__device__ __forceinline__ void ldg256(const float* p, float* v) {
    asm volatile(
        "ld.global.v8.f32 {%0, %1, %2, %3, %4, %5, %6, %7}, [%8];"
        : "=f"(v[0]), "=f"(v[1]), "=f"(v[2]), "=f"(v[3]),
          "=f"(v[4]), "=f"(v[5]), "=f"(v[6]), "=f"(v[7])
        : "l"(p));
}

__device__ __forceinline__ void stg256(float* p, const float* v) {
    asm volatile(
        "st.global.v8.f32 [%0], {%1, %2, %3, %4, %5, %6, %7, %8};"
        :: "l"(p),
           "f"(v[0]), "f"(v[1]), "f"(v[2]), "f"(v[3]),
           "f"(v[4]), "f"(v[5]), "f"(v[6]), "f"(v[7])
        : "memory");
}

__global__ __launch_bounds__(256) void lif_kernel(
    const float* __restrict__ x,
    const float* __restrict__ noise,
    float* __restrict__ out)
{
    int idx = blockIdx.x * blockDim.x + threadIdx.x;   // 0 .. B*N8-1 (exact)

    int b  = idx >> 13;          // / N8 (8192)
    int n8 = idx & (N8 - 1);     // % N8

    const size_t base = (size_t)b * T * N + (size_t)n8 * 8;
    const float* __restrict__ xp = x     + base;
    const float* __restrict__ np = noise + base;
    float*       __restrict__ op = out   + base;

    float u[8];
#pragma unroll
    for (int i = 0; i < 8; i++) u[i] = 0.f;

#pragma unroll
    for (int t = 0; t < T; t++) {
        float xv[8], nv[8], o[8];
        ldg256(xp + (size_t)t * N, xv);
        ldg256(np + (size_t)t * N, nv);

#pragma unroll
        for (int i = 0; i < 8; i++) {
            u[i] = fmaf(-0.5f, nv[i], fmaf(0.5f, u[i], xv[i]));
            o[i] = (u[i] > 1.0f) ? 1.0f : 0.0f;
            u[i] = (u[i] > 1.0f) ? 0.0f : u[i];
        }

        stg256(op + (size_t)t * N, o);
    }
}

extern "C" void kernel_launch(void* const* d_in, const int* in_sizes, int n_in,
                              void* d_out, int out_size)
{
    const float* x     = (const float*)d_in[0];
    const float* noise = (const float*)d_in[1];
    float*       out   = (float*)d_out;

    const int total_threads = B * N8;        // 131072
    const int tpb = 256;
    const int blocks = total_threads / tpb;  // 512, exact

    lif_kernel<<<blocks, tpb>>>(x, noise, out);
}